// round 14
// baseline (speedup 1.0000x reference)
#include <cuda_runtime.h>
#include <cuda_fp16.h>
#include <math.h>
#include <stdint.h>

#define BB 4
#define SS 2048
#define DD 1024

// ---------------- device scratch ----------------
__device__ __half g_xh[BB * SS * DD];
__device__ __half g_Wqh[DD * DD];
__device__ __half g_Wkvh[2 * DD * DD];         // [Wk ; Wv] concat
__device__ __half g_Qh[BB * SS * DD];
__device__ __half g_Kc[BB * SS * DD];          // compacted K
__device__ __half g_Vtc[BB * SS * DD];         // compacted V, [B][D][j]
__device__ __half g_Ph[(size_t)BB * SS * SS];  // unnormalized exp(logit), fp16
__device__ float  g_rsum[BB * SS];
__device__ int    g_idx[BB * SS];              // kept-row indices, padded with 0
__device__ int    g_nkeep[BB];
__device__ int    g_npad[BB];                  // 128-aligned (CTA skip)
__device__ int    g_kd64[BB];                  // 64-aligned (attn.V K-dim)

// ---------------- helpers ----------------
__device__ __forceinline__ uint32_t smem_u32(const void* p) {
    uint32_t a;
    asm("{ .reg .u64 t; cvta.to.shared.u64 t, %1; cvt.u32.u64 %0, t; }" : "=r"(a) : "l"(p));
    return a;
}
__device__ __forceinline__ void cp16(uint32_t s, const void* g) {
    asm volatile("cp.async.cg.shared.global [%0], [%1], 16;" :: "r"(s), "l"(g) : "memory");
}
#define CP_COMMIT() asm volatile("cp.async.commit_group;" ::: "memory")
#define CP_WAIT(n)  asm volatile("cp.async.wait_group %0;" :: "n"(n) : "memory")

__device__ __forceinline__ void ldm4(uint32_t* r, uint32_t a) {
    asm volatile("ldmatrix.sync.aligned.m8n8.x4.shared.b16 {%0,%1,%2,%3}, [%4];"
                 : "=r"(r[0]), "=r"(r[1]), "=r"(r[2]), "=r"(r[3]) : "r"(a));
}
__device__ __forceinline__ void mma16816(float* d, const uint32_t* a, uint32_t b0, uint32_t b1) {
    asm volatile(
        "mma.sync.aligned.m16n8k16.row.col.f32.f16.f16.f32 "
        "{%0,%1,%2,%3}, {%4,%5,%6,%7}, {%8,%9}, {%0,%1,%2,%3};"
        : "+f"(d[0]), "+f"(d[1]), "+f"(d[2]), "+f"(d[3])
        : "r"(a[0]), "r"(a[1]), "r"(a[2]), "r"(a[3]), "r"(b0), "r"(b1));
}

// ---------------------------------------------------------------------------
// Plain-fp16 NT GEMM core: CTA 128x128, 8 warps (64x32), k-tile 64,
// 3-stage cp.async (load AFTER the barrier -> one sync per k-iter is safe:
// load(kt+2) writes the stage last read by compute(kt-1), and the sync at
// iter kt orders all warps past compute(kt-1) before the load).
// 2 CTAs/SM (108KB smem/CTA). Per-thread load pointers hoisted.
// EPIs:
//  EPI 5: scores: Ph = exp(alpha*acc) fp16 (cols >= nkeep -> 0), rsum atomics
//  EPI 6: attn.V: fp32 store scaled by 1/rsum[row]
//  EPI 7: merged projections: bz<BB -> K|V proj, A rows gathered via gidx;
//         bz>=BB -> Q proj row-segment (bz-BB)*2048
// ---------------------------------------------------------------------------
static constexpr int ATILE  = 18432;             // 128 rows x 72 halves x 2B
static constexpr int STG    = 2 * ATILE;         // 36864
static constexpr int STAGES = 3;
static constexpr int SMEMB  = STAGES * STG;      // 110592

template <int EPI>
__global__ __launch_bounds__(256, 2)
void hgemm(const __half* __restrict__ Ah, const __half* __restrict__ Bh,
           const float* __restrict__ bias, const float* __restrict__ bias2,
           float* __restrict__ Cf, __half* __restrict__ Ch, __half* __restrict__ Ch2,
           float* __restrict__ rbuf, const int* __restrict__ nKeepA,
           int lda, int ldb, int ldc, int K, float alpha,
           long long sA, long long sB, long long sC,
           const int* __restrict__ mLim, const int* __restrict__ nLim,
           const int* __restrict__ kd, const int* __restrict__ gidx,
           const __half* __restrict__ qA, const __half* __restrict__ qB,
           const float* __restrict__ qbias, __half* __restrict__ qC)
{
    extern __shared__ char smem[];
    const uint32_t sbase = smem_u32(smem);
    const int t    = threadIdx.x;
    const int lane = t & 31;
    const int wid  = t >> 5;
    const int wm   = wid >> 2;
    const int wn   = wid & 3;
    const int lr   = lane & 15;
    const int lh   = lane >> 4;

    const long long bz = blockIdx.z;
    const int row0 = blockIdx.y * 128;
    const int col0 = blockIdx.x * 128;

    bool qmode = false;
    if (EPI == 7) {
        if (bz >= BB) {
            qmode = true;
            if (col0 >= DD) return;
            Ah = qA + (size_t)(bz - BB) * 2048 * DD;
            Bh = qB;
        } else {
            if (row0 >= mLim[bz]) return;
            Ah += bz * sA;
        }
    } else {
        if (mLim && row0 >= mLim[bz]) return;
        if (nLim && col0 >= nLim[bz]) return;
        if (kd) K = kd[bz];
        Ah += bz * sA;
        Bh += bz * sB;
        if (Cf)  Cf  += bz * sC;
        if (Ch)  Ch  += bz * sC;
        if (rbuf) rbuf += bz * SS;
    }

    // ---- hoisted per-thread load pointers (4 A rows + 4 B rows, 16B each) ----
    const int ch8 = (t & 7) * 8;         // halves
    const int rr  = t >> 3;              // 0..31
    int ar0 = row0 + rr, ar1 = row0 + 32 + rr, ar2 = row0 + 64 + rr, ar3 = row0 + 96 + rr;
    if (EPI == 7 && !qmode) {
        const int* ib = gidx + bz * SS;
        ar0 = ib[ar0]; ar1 = ib[ar1]; ar2 = ib[ar2]; ar3 = ib[ar3];
    }
    const __half* ap0 = Ah + (size_t)ar0 * lda + ch8;
    const __half* ap1 = Ah + (size_t)ar1 * lda + ch8;
    const __half* ap2 = Ah + (size_t)ar2 * lda + ch8;
    const __half* ap3 = Ah + (size_t)ar3 * lda + ch8;
    const __half* bp0 = Bh + (size_t)(col0 + rr) * ldb + ch8;
    const __half* bp1 = Bh + (size_t)(col0 + 32 + rr) * ldb + ch8;
    const __half* bp2 = Bh + (size_t)(col0 + 64 + rr) * ldb + ch8;
    const __half* bp3 = Bh + (size_t)(col0 + 96 + rr) * ldb + ch8;
    const uint32_t so0 = (uint32_t)((rr      ) * 144 + (t & 7) * 16);
    const uint32_t so1 = (uint32_t)((rr + 32 ) * 144 + (t & 7) * 16);
    const uint32_t so2 = (uint32_t)((rr + 64 ) * 144 + (t & 7) * 16);
    const uint32_t so3 = (uint32_t)((rr + 96 ) * 144 + (t & 7) * 16);

    float acc[4][4][4];
#pragma unroll
    for (int i = 0; i < 4; i++)
#pragma unroll
        for (int j = 0; j < 4; j++)
#pragma unroll
            for (int r = 0; r < 4; r++) acc[i][j][r] = 0.0f;

    auto load_tile = [&](int jt, int s) {
        const uint32_t dstb = sbase + s * STG;
        const int o = jt * 64;
        cp16(dstb + so0, ap0 + o);
        cp16(dstb + so1, ap1 + o);
        cp16(dstb + so2, ap2 + o);
        cp16(dstb + so3, ap3 + o);
        cp16(dstb + ATILE + so0, bp0 + o);
        cp16(dstb + ATILE + so1, bp1 + o);
        cp16(dstb + ATILE + so2, bp2 + o);
        cp16(dstb + ATILE + so3, bp3 + o);
    };

    auto compute = [&](uint32_t sb) {
#pragma unroll
        for (int kb = 0; kb < 4; kb++) {
            const int kk = kb * 16;
            uint32_t ah[4][4], bh[2][4];
#pragma unroll
            for (int i = 0; i < 4; i++) {
                uint32_t ra = (uint32_t)(((wm * 64 + i * 16 + lr) * 72 + kk + 8 * lh) * 2);
                ldm4(ah[i], sb + ra);
            }
#pragma unroll
            for (int j2 = 0; j2 < 2; j2++) {
                uint32_t rb = (uint32_t)(((wn * 32 + j2 * 16 + lr) * 72 + kk + 8 * lh) * 2);
                ldm4(bh[j2], sb + ATILE + rb);
            }
#pragma unroll
            for (int i = 0; i < 4; i++)
#pragma unroll
                for (int j = 0; j < 4; j++) {
                    const int j2 = j >> 1, sl = j & 1;
                    mma16816(acc[i][j], ah[i], bh[j2][sl], bh[j2][sl + 2]);
                }
        }
    };

    const int KT = K >> 6;
    load_tile(0, 0); CP_COMMIT();
    load_tile(1, 1); CP_COMMIT();

    for (int kt = 0; kt < KT; kt++) {
        if (kt + 2 < KT) {
            CP_WAIT(1);              // group kt complete (kt+1 may be in flight)
            __syncthreads();         // all warps done with compute(kt-1)
            load_tile(kt + 2, (kt + 2) % 3);
            CP_COMMIT();
        } else if (kt + 1 < KT) {
            CP_WAIT(1);
            __syncthreads();
        } else {
            CP_WAIT(0);
            __syncthreads();
        }
        compute(sbase + (uint32_t)((kt % 3) * STG));
    }

    // ---------------- epilogue ----------------
    const int g  = lane >> 2;
    const int tq = lane & 3;

    if (EPI == 7) {
        if (qmode) {
            __half* C = qC + (size_t)(bz - BB) * 2048 * DD;
#pragma unroll
            for (int i = 0; i < 4; i++) {
                int r0 = row0 + wm * 64 + i * 16 + g;
#pragma unroll
                for (int j = 0; j < 4; j++) {
                    int c = col0 + wn * 32 + j * 8 + tq * 2;
                    float bx = qbias[c], by = qbias[c + 1];
#pragma unroll
                    for (int h = 0; h < 2; h++) {
                        float vx = acc[i][j][2 * h + 0] + bx;
                        float vy = acc[i][j][2 * h + 1] + by;
                        size_t off = (size_t)(r0 + 8 * h) * DD + c;
                        *(__half2*)(C + off) =
                            __halves2half2(__float2half_rn(vx), __float2half_rn(vy));
                    }
                }
            }
        } else if (col0 < DD) {
            // K path
            __half* C = Ch + bz * sC;
#pragma unroll
            for (int i = 0; i < 4; i++) {
                int r0 = row0 + wm * 64 + i * 16 + g;
#pragma unroll
                for (int j = 0; j < 4; j++) {
                    int c = col0 + wn * 32 + j * 8 + tq * 2;
                    float bx = bias[c], by = bias[c + 1];
#pragma unroll
                    for (int h = 0; h < 2; h++) {
                        float vx = acc[i][j][2 * h + 0] + bx;
                        float vy = acc[i][j][2 * h + 1] + by;
                        size_t off = (size_t)(r0 + 8 * h) * DD + c;
                        *(__half2*)(C + off) =
                            __halves2half2(__float2half_rn(vx), __float2half_rn(vy));
                    }
                }
            }
        } else {
            // V path: transpose to Vtc[d][j]
            __syncthreads();
            __half* hs = (__half*)smem;             // [128][136]
            const int d0 = col0 - DD;
            __half* C2 = Ch2 + bz * sC;
#pragma unroll
            for (int i = 0; i < 4; i++) {
                int m0 = wm * 64 + i * 16 + g;
#pragma unroll
                for (int j = 0; j < 4; j++) {
                    int c = wn * 32 + j * 8 + tq * 2;
                    float bx = bias2[d0 + c], by = bias2[d0 + c + 1];
#pragma unroll
                    for (int h = 0; h < 2; h++) {
                        int m = m0 + 8 * h;
                        hs[(c + 0) * 136 + m] = __float2half_rn(acc[i][j][2 * h + 0] + bx);
                        hs[(c + 1) * 136 + m] = __float2half_rn(acc[i][j][2 * h + 1] + by);
                    }
                }
            }
            __syncthreads();
            const int cb = t >> 5;
            const int m  = (t & 31) * 4;
#pragma unroll 4
            for (int cc = cb; cc < 128; cc += 8) {
                size_t off = (size_t)(d0 + cc) * SS + row0 + m;
                *(__half2*)(C2 + off)     = *(__half2*)(hs + cc * 136 + m);
                *(__half2*)(C2 + off + 2) = *(__half2*)(hs + cc * 136 + m + 2);
            }
        }
    } else if (EPI == 5) {
        const int nk = nKeepA[bz];
#pragma unroll
        for (int i = 0; i < 4; i++) {
            int r0 = row0 + wm * 64 + i * 16 + g;
            float s0 = 0.0f, s1 = 0.0f;
#pragma unroll
            for (int j = 0; j < 4; j++) {
                int c = col0 + wn * 32 + j * 8 + tq * 2;
                float e0 = (c     < nk) ? __expf(acc[i][j][0] * alpha) : 0.0f;
                float e1 = (c + 1 < nk) ? __expf(acc[i][j][1] * alpha) : 0.0f;
                float e2 = (c     < nk) ? __expf(acc[i][j][2] * alpha) : 0.0f;
                float e3 = (c + 1 < nk) ? __expf(acc[i][j][3] * alpha) : 0.0f;
                s0 += e0 + e1;
                s1 += e2 + e3;
                *(__half2*)(Ch + (size_t)r0 * SS + c) =
                    __halves2half2(__float2half_rn(e0), __float2half_rn(e1));
                *(__half2*)(Ch + (size_t)(r0 + 8) * SS + c) =
                    __halves2half2(__float2half_rn(e2), __float2half_rn(e3));
            }
            s0 += __shfl_xor_sync(0xffffffffu, s0, 1);
            s0 += __shfl_xor_sync(0xffffffffu, s0, 2);
            s1 += __shfl_xor_sync(0xffffffffu, s1, 1);
            s1 += __shfl_xor_sync(0xffffffffu, s1, 2);
            if (tq == 0) {
                atomicAdd(rbuf + r0, s0);
                atomicAdd(rbuf + r0 + 8, s1);
            }
        }
    } else {  // EPI == 6 : out = acc / rsum[row]
#pragma unroll
        for (int i = 0; i < 4; i++) {
            int r0 = row0 + wm * 64 + i * 16 + g;
            float v0s = 1.0f / rbuf[r0];
            float v1s = 1.0f / rbuf[r0 + 8];
#pragma unroll
            for (int j = 0; j < 4; j++) {
                int c = col0 + wn * 32 + j * 8 + tq * 2;
                float2 v0 = make_float2(acc[i][j][0] * v0s, acc[i][j][1] * v0s);
                float2 v1 = make_float2(acc[i][j][2] * v1s, acc[i][j][3] * v1s);
                *(float2*)(Cf + (size_t)r0 * ldc + c)       = v0;
                *(float2*)(Cf + (size_t)(r0 + 8) * ldc + c) = v1;
            }
        }
    }
}

// ---------------------------------------------------------------------------
// Single prep kernel:
//  blocks 0..BB-1 : per-batch compaction (+ idx pad with 0, rsum zero,
//                   npad/kd64 computation)
//  blocks >= BB   : grid-stride fp32->fp16 convert of x + 3 weight matrices
// ---------------------------------------------------------------------------
static constexpr int CVT_F4   = 2883584;         // (8M + 3M) / 4
static constexpr int PREP_CVT = 1024;            // convert blocks

__global__ __launch_bounds__(256)
void prep_kernel(const int* __restrict__ mask, int* __restrict__ idx,
                 int* __restrict__ nkeepA, int* __restrict__ npadA,
                 int* __restrict__ kd64A, float* __restrict__ rsum,
                 const float* __restrict__ x,
                 const float* __restrict__ Wq, const float* __restrict__ Wk,
                 const float* __restrict__ Wv,
                 __half* __restrict__ xh, __half* __restrict__ Wqh,
                 __half* __restrict__ Wkvh)
{
    const int t = threadIdx.x;
    if (blockIdx.x < BB) {
        const int b = blockIdx.x;
        const int* m = mask + (size_t)b * SS;
        int* idxb = idx + (size_t)b * SS;
        __shared__ int cnt[257];
        int loc[8], c = 0;
#pragma unroll
        for (int i = 0; i < 8; i++) {
            loc[i] = (m[t * 8 + i] != 0);
            c += loc[i];
        }
        cnt[t + 1] = c;
        if (t == 0) cnt[0] = 0;
        __syncthreads();
        if (t == 0)
            for (int i = 1; i <= 256; i++) cnt[i] += cnt[i - 1];
        __syncthreads();
        int base = cnt[t];
#pragma unroll
        for (int i = 0; i < 8; i++)
            if (loc[i]) idxb[base++] = t * 8 + i;
        const int tot = cnt[256];
        // pad remaining index slots with 0 (its K/V values meet exactly-zero
        // probabilities, so any finite row index is correct)
        for (int i = tot + t; i < SS; i += 256) idxb[i] = 0;
        if (t == 0) {
            nkeepA[b] = tot;
            npadA[b]  = (tot + 127) & ~127;
            kd64A[b]  = (tot + 63) & ~63;
        }
        float4 z = make_float4(0.f, 0.f, 0.f, 0.f);
        ((float4*)rsum)[(b * 256 + t) * 2 + 0] = z;
        ((float4*)rsum)[(b * 256 + t) * 2 + 1] = z;
    } else {
        const int cblk = blockIdx.x - BB;
        for (int i = cblk * 256 + t; i < CVT_F4; i += PREP_CVT * 256) {
            const float* src;
            __half* dst;
            int k;
            if (i < 2097152) { src = x; dst = xh; k = i; }
            else {
                int j = i - 2097152;
                int w = j >> 18;
                k = j & 262143;
                src = (w == 0) ? Wq : (w == 1) ? Wk : Wv;
                dst = (w == 0) ? Wqh : (w == 1) ? Wkvh : (Wkvh + DD * DD);
            }
            float4 v = ((const float4*)src)[k];
            ((__half2*)dst)[2 * k + 0] =
                __halves2half2(__float2half_rn(v.x), __float2half_rn(v.y));
            ((__half2*)dst)[2 * k + 1] =
                __halves2half2(__float2half_rn(v.z), __float2half_rn(v.w));
        }
    }
}

// ---------------------------------------------------------------------------
extern "C" void kernel_launch(void* const* d_in, const int* in_sizes, int n_in,
                              void* d_out, int out_size)
{
    const float* x    = (const float*)d_in[0];
    const int*   mask = (const int*)  d_in[1];
    const float* Wq   = (const float*)d_in[2];
    const float* bq   = (const float*)d_in[3];
    const float* Wk   = (const float*)d_in[4];
    const float* bk   = (const float*)d_in[5];
    const float* Wv   = (const float*)d_in[6];
    const float* bv   = (const float*)d_in[7];
    float* out = (float*)d_out;

    __half *xh, *Wqh, *Wkvh, *Qh, *Kc, *Vtc, *Ph;
    float* rsum;
    int *idx, *nkeep, *npad, *kd64;
    cudaGetSymbolAddress((void**)&xh,   g_xh);
    cudaGetSymbolAddress((void**)&Wqh,  g_Wqh);
    cudaGetSymbolAddress((void**)&Wkvh, g_Wkvh);
    cudaGetSymbolAddress((void**)&Qh,   g_Qh);
    cudaGetSymbolAddress((void**)&Kc,   g_Kc);
    cudaGetSymbolAddress((void**)&Vtc,  g_Vtc);
    cudaGetSymbolAddress((void**)&Ph,   g_Ph);
    cudaGetSymbolAddress((void**)&rsum, g_rsum);
    cudaGetSymbolAddress((void**)&idx,  g_idx);
    cudaGetSymbolAddress((void**)&nkeep, g_nkeep);
    cudaGetSymbolAddress((void**)&npad, g_npad);
    cudaGetSymbolAddress((void**)&kd64, g_kd64);

    cudaFuncSetAttribute(hgemm<5>, cudaFuncAttributeMaxDynamicSharedMemorySize, SMEMB);
    cudaFuncSetAttribute(hgemm<6>, cudaFuncAttributeMaxDynamicSharedMemorySize, SMEMB);
    cudaFuncSetAttribute(hgemm<7>, cudaFuncAttributeMaxDynamicSharedMemorySize, SMEMB);

    const long long sBD = (long long)SS * DD;
    const long long sSS = (long long)SS * SS;

    // #0: compaction + rsum zero + converts (one launch)
    prep_kernel<<<BB + PREP_CVT, 256>>>(mask, idx, nkeep, npad, kd64, rsum,
                                        x, Wq, Wk, Wv, xh, Wqh, Wkvh);

    // #1: merged Q + K|V projections (KV gathers A rows through idx)
    {
        dim3 g(2 * DD / 128, SS / 128, 2 * BB);
        hgemm<7><<<g, 256, SMEMB>>>(xh, Wkvh, bk, bv, nullptr, Kc, Vtc,
                                    nullptr, nullptr,
                                    DD, DD, DD, DD, 1.0f, sBD, 0, sBD,
                                    npad, nullptr, nullptr, idx,
                                    xh, Wqh, bq, Qh);
    }

    // #2: scores -> unnormalized exp fp16 + row sums
    {
        dim3 g(SS / 128, SS / 128, BB);
        hgemm<5><<<g, 256, SMEMB>>>(Qh, Kc, nullptr, nullptr, nullptr, Ph, nullptr,
                                    rsum, nkeep,
                                    DD, DD, SS, DD, 1.0f / 32.0f,
                                    sBD, sBD, sSS,
                                    nullptr, npad, nullptr, nullptr,
                                    nullptr, nullptr, nullptr, nullptr);
    }

    // #3: out = (E @ Vtc^T) / rsum[row], dynamic K = kd64[b]
    {
        dim3 g(DD / 128, SS / 128, BB);
        hgemm<6><<<g, 256, SMEMB>>>(Ph, Vtc, nullptr, nullptr, out, nullptr, nullptr,
                                    rsum, nullptr,
                                    SS, SS, DD, DD, 1.0f,
                                    sSS, sBD, sBD,
                                    nullptr, nullptr, kd64, nullptr,
                                    nullptr, nullptr, nullptr, nullptr);
    }
}

// round 15
// speedup vs baseline: 1.0139x; 1.0139x over previous
#include <cuda_runtime.h>
#include <cuda_fp16.h>
#include <math.h>
#include <stdint.h>

#define BB 4
#define SS 2048
#define DD 1024

// ---------------- device scratch ----------------
__device__ __half g_xh[BB * SS * DD];
__device__ __half g_Wqh[DD * DD];
__device__ __half g_Wkvh[2 * DD * DD];         // [Wk ; Wv] concat
__device__ __half g_Qh[BB * SS * DD];
__device__ __half g_Kc[BB * SS * DD];          // compacted K
__device__ __half g_Vtc[BB * SS * DD];         // compacted V, [B][D][j]
__device__ __half g_Ph[(size_t)BB * SS * SS];  // unnormalized exp(logit), fp16
__device__ float  g_rsum[BB * SS];
__device__ int    g_idx[BB * SS];              // kept-row indices, padded with 0
__device__ int    g_nkeep[BB];
__device__ int    g_npad[BB];                  // 128-aligned (CTA skip)
__device__ int    g_kd32[BB];                  // 32-aligned (attn.V K-dim)

// ---------------- helpers ----------------
__device__ __forceinline__ uint32_t smem_u32(const void* p) {
    uint32_t a;
    asm("{ .reg .u64 t; cvta.to.shared.u64 t, %1; cvt.u32.u64 %0, t; }" : "=r"(a) : "l"(p));
    return a;
}
__device__ __forceinline__ void cp16(uint32_t s, const void* g) {
    asm volatile("cp.async.cg.shared.global [%0], [%1], 16;" :: "r"(s), "l"(g) : "memory");
}
#define CP_COMMIT() asm volatile("cp.async.commit_group;" ::: "memory")
#define CP_WAIT(n)  asm volatile("cp.async.wait_group %0;" :: "n"(n) : "memory")

__device__ __forceinline__ void ldm4(uint32_t* r, uint32_t a) {
    asm volatile("ldmatrix.sync.aligned.m8n8.x4.shared.b16 {%0,%1,%2,%3}, [%4];"
                 : "=r"(r[0]), "=r"(r[1]), "=r"(r[2]), "=r"(r[3]) : "r"(a));
}
__device__ __forceinline__ void mma16816(float* d, const uint32_t* a, uint32_t b0, uint32_t b1) {
    asm volatile(
        "mma.sync.aligned.m16n8k16.row.col.f32.f16.f16.f32 "
        "{%0,%1,%2,%3}, {%4,%5,%6,%7}, {%8,%9}, {%0,%1,%2,%3};"
        : "+f"(d[0]), "+f"(d[1]), "+f"(d[2]), "+f"(d[3])
        : "r"(a[0]), "r"(a[1]), "r"(a[2]), "r"(a[3]), "r"(b0), "r"(b1));
}

// ---------------------------------------------------------------------------
// Plain-fp16 NT GEMM core (R13 config: CTA 128x128, 8 warps 64x32, k-tile 32,
// 4-stage cp.async, one __syncthreads/k-iter, 2 CTAs/SM, hoisted pointers).
// EPIs:
//  EPI 5: scores: Ph = exp(alpha*acc) fp16 (cols >= nkeep -> 0), rsum atomics
//  EPI 6: attn.V: fp32 store scaled by 1/rsum[row]
//  EPI 7: merged projections, packed grid (z in [0,6)):
//         bz<BB  -> K|V proj batch bz, A rows gathered via gidx
//         bz>=BB -> Q proj segment seg=(bz-BB)*2 + (col0>=DD), col0q=col0&1023
// ---------------------------------------------------------------------------
static constexpr int STG    = 20480;
static constexpr int STAGES = 4;
static constexpr int SMEMB  = STAGES * STG;      // 81920

template <int EPI>
__global__ __launch_bounds__(256, 2)
void hgemm(const __half* __restrict__ Ah, const __half* __restrict__ Bh,
           const float* __restrict__ bias, const float* __restrict__ bias2,
           float* __restrict__ Cf, __half* __restrict__ Ch, __half* __restrict__ Ch2,
           float* __restrict__ rbuf, const int* __restrict__ nKeepA,
           int lda, int ldb, int ldc, int K, float alpha,
           long long sA, long long sB, long long sC,
           const int* __restrict__ mLim, const int* __restrict__ nLim,
           const int* __restrict__ kd, const int* __restrict__ gidx,
           const __half* __restrict__ qA, const __half* __restrict__ qB,
           const float* __restrict__ qbias, __half* __restrict__ qC)
{
    extern __shared__ char smem[];
    const uint32_t sbase = smem_u32(smem);
    const int t    = threadIdx.x;
    const int lane = t & 31;
    const int wid  = t >> 5;
    const int wm   = wid >> 2;
    const int wn   = wid & 3;
    const int lr   = lane & 15;
    const int lh   = lane >> 4;

    const long long bz = blockIdx.z;
    const int row0 = blockIdx.y * 128;
    const int col0 = blockIdx.x * 128;

    bool qmode = false;
    int col0b = col0;          // B-operand / output column base
    int qseg  = 0;
    if (EPI == 7) {
        if (bz >= BB) {
            qmode = true;
            qseg  = (int)(bz - BB) * 2 + (col0 >= DD ? 1 : 0);
            col0b = col0 & (DD - 1);
            Ah = qA + (size_t)qseg * 2048 * DD;
            Bh = qB;
        } else {
            if (row0 >= mLim[bz]) return;
            Ah += bz * sA;
        }
    } else {
        if (mLim && row0 >= mLim[bz]) return;
        if (nLim && col0 >= nLim[bz]) return;
        if (kd) K = kd[bz];
        Ah += bz * sA;
        Bh += bz * sB;
        if (Cf)  Cf  += bz * sC;
        if (Ch)  Ch  += bz * sC;
        if (rbuf) rbuf += bz * SS;
    }

    // ---- hoisted per-thread load pointers ----
    const int ch = t & 3;
    const int rr = t >> 2;               // 0..63
    int ar0 = row0 + rr, ar1 = row0 + 64 + rr;
    if (EPI == 7 && !qmode) {
        const int* ib = gidx + bz * SS;
        ar0 = ib[ar0];
        ar1 = ib[ar1];
    }
    const __half* ap0 = Ah + (size_t)ar0 * lda + ch * 8;
    const __half* ap1 = Ah + (size_t)ar1 * lda + ch * 8;
    const __half* bp0 = Bh + (size_t)(col0b + rr) * ldb + ch * 8;
    const __half* bp1 = Bh + (size_t)(col0b + 64 + rr) * ldb + ch * 8;
    const uint32_t so0 = (uint32_t)(rr * 80 + ch * 16);
    const uint32_t so1 = (uint32_t)((64 + rr) * 80 + ch * 16);

    float acc[4][4][4];
#pragma unroll
    for (int i = 0; i < 4; i++)
#pragma unroll
        for (int j = 0; j < 4; j++)
#pragma unroll
            for (int r = 0; r < 4; r++) acc[i][j][r] = 0.0f;

    auto load_tile = [&](int jt, int s) {
        const uint32_t dstb = sbase + s * STG;
        const int o = jt * 32;
        cp16(dstb + so0,          ap0 + o);
        cp16(dstb + so1,          ap1 + o);
        cp16(dstb + 10240u + so0, bp0 + o);
        cp16(dstb + 10240u + so1, bp1 + o);
    };

    auto compute = [&](uint32_t sb) {
#pragma unroll
        for (int kk = 0; kk < 32; kk += 16) {
            uint32_t ah[4][4], bh[2][4];
#pragma unroll
            for (int i = 0; i < 4; i++) {
                uint32_t ra = (uint32_t)(((wm * 64 + i * 16 + lr) * 40 + kk + 8 * lh) * 2);
                ldm4(ah[i], sb + ra);
            }
#pragma unroll
            for (int j2 = 0; j2 < 2; j2++) {
                uint32_t rb = (uint32_t)(((wn * 32 + j2 * 16 + lr) * 40 + kk + 8 * lh) * 2);
                ldm4(bh[j2], sb + 10240u + rb);
            }
#pragma unroll
            for (int i = 0; i < 4; i++)
#pragma unroll
                for (int j = 0; j < 4; j++) {
                    const int j2 = j >> 1, sl = j & 1;
                    mma16816(acc[i][j], ah[i], bh[j2][sl], bh[j2][sl + 2]);
                }
        }
    };

    const int KT = K >> 5;
    load_tile(0, 0); CP_COMMIT();
    load_tile(1, 1); CP_COMMIT();

    for (int kt = 0; kt < KT; kt++) {
        const int j = kt + 2;
        if (j < KT) load_tile(j, j & 3);
        CP_COMMIT();
        CP_WAIT(2);
        __syncthreads();
        compute(sbase + (uint32_t)((kt & 3) * STG));
    }

    // ---------------- epilogue ----------------
    const int g  = lane >> 2;
    const int tq = lane & 3;

    if (EPI == 7) {
        if (qmode) {
            __half* C = qC + (size_t)qseg * 2048 * DD;
#pragma unroll
            for (int i = 0; i < 4; i++) {
                int r0 = row0 + wm * 64 + i * 16 + g;
#pragma unroll
                for (int j = 0; j < 4; j++) {
                    int c = col0b + wn * 32 + j * 8 + tq * 2;
                    float bx = qbias[c], by = qbias[c + 1];
#pragma unroll
                    for (int h = 0; h < 2; h++) {
                        float vx = acc[i][j][2 * h + 0] + bx;
                        float vy = acc[i][j][2 * h + 1] + by;
                        size_t off = (size_t)(r0 + 8 * h) * DD + c;
                        *(__half2*)(C + off) =
                            __halves2half2(__float2half_rn(vx), __float2half_rn(vy));
                    }
                }
            }
        } else if (col0 < DD) {
            // K path
            __half* C = Ch + bz * sC;
#pragma unroll
            for (int i = 0; i < 4; i++) {
                int r0 = row0 + wm * 64 + i * 16 + g;
#pragma unroll
                for (int j = 0; j < 4; j++) {
                    int c = col0 + wn * 32 + j * 8 + tq * 2;
                    float bx = bias[c], by = bias[c + 1];
#pragma unroll
                    for (int h = 0; h < 2; h++) {
                        float vx = acc[i][j][2 * h + 0] + bx;
                        float vy = acc[i][j][2 * h + 1] + by;
                        size_t off = (size_t)(r0 + 8 * h) * DD + c;
                        *(__half2*)(C + off) =
                            __halves2half2(__float2half_rn(vx), __float2half_rn(vy));
                    }
                }
            }
        } else {
            // V path: transpose to Vtc[d][j]
            __syncthreads();
            __half* hs = (__half*)smem;             // [128][136]
            const int d0 = col0 - DD;
            __half* C2 = Ch2 + bz * sC;
#pragma unroll
            for (int i = 0; i < 4; i++) {
                int m0 = wm * 64 + i * 16 + g;
#pragma unroll
                for (int j = 0; j < 4; j++) {
                    int c = wn * 32 + j * 8 + tq * 2;
                    float bx = bias2[d0 + c], by = bias2[d0 + c + 1];
#pragma unroll
                    for (int h = 0; h < 2; h++) {
                        int m = m0 + 8 * h;
                        hs[(c + 0) * 136 + m] = __float2half_rn(acc[i][j][2 * h + 0] + bx);
                        hs[(c + 1) * 136 + m] = __float2half_rn(acc[i][j][2 * h + 1] + by);
                    }
                }
            }
            __syncthreads();
            const int cb = t >> 5;
            const int m  = (t & 31) * 4;
#pragma unroll 4
            for (int cc = cb; cc < 128; cc += 8) {
                size_t off = (size_t)(d0 + cc) * SS + row0 + m;
                *(__half2*)(C2 + off)     = *(__half2*)(hs + cc * 136 + m);
                *(__half2*)(C2 + off + 2) = *(__half2*)(hs + cc * 136 + m + 2);
            }
        }
    } else if (EPI == 5) {
        const int nk = nKeepA[bz];
#pragma unroll
        for (int i = 0; i < 4; i++) {
            int r0 = row0 + wm * 64 + i * 16 + g;
            float s0 = 0.0f, s1 = 0.0f;
#pragma unroll
            for (int j = 0; j < 4; j++) {
                int c = col0 + wn * 32 + j * 8 + tq * 2;
                float e0 = (c     < nk) ? __expf(acc[i][j][0] * alpha) : 0.0f;
                float e1 = (c + 1 < nk) ? __expf(acc[i][j][1] * alpha) : 0.0f;
                float e2 = (c     < nk) ? __expf(acc[i][j][2] * alpha) : 0.0f;
                float e3 = (c + 1 < nk) ? __expf(acc[i][j][3] * alpha) : 0.0f;
                s0 += e0 + e1;
                s1 += e2 + e3;
                *(__half2*)(Ch + (size_t)r0 * SS + c) =
                    __halves2half2(__float2half_rn(e0), __float2half_rn(e1));
                *(__half2*)(Ch + (size_t)(r0 + 8) * SS + c) =
                    __halves2half2(__float2half_rn(e2), __float2half_rn(e3));
            }
            s0 += __shfl_xor_sync(0xffffffffu, s0, 1);
            s0 += __shfl_xor_sync(0xffffffffu, s0, 2);
            s1 += __shfl_xor_sync(0xffffffffu, s1, 1);
            s1 += __shfl_xor_sync(0xffffffffu, s1, 2);
            if (tq == 0) {
                atomicAdd(rbuf + r0, s0);
                atomicAdd(rbuf + r0 + 8, s1);
            }
        }
    } else {  // EPI == 6 : out = acc / rsum[row]
#pragma unroll
        for (int i = 0; i < 4; i++) {
            int r0 = row0 + wm * 64 + i * 16 + g;
            float v0s = 1.0f / rbuf[r0];
            float v1s = 1.0f / rbuf[r0 + 8];
#pragma unroll
            for (int j = 0; j < 4; j++) {
                int c = col0 + wn * 32 + j * 8 + tq * 2;
                float2 v0 = make_float2(acc[i][j][0] * v0s, acc[i][j][1] * v0s);
                float2 v1 = make_float2(acc[i][j][2] * v1s, acc[i][j][3] * v1s);
                *(float2*)(Cf + (size_t)r0 * ldc + c)       = v0;
                *(float2*)(Cf + (size_t)(r0 + 8) * ldc + c) = v1;
            }
        }
    }
}

// ---------------------------------------------------------------------------
// Single prep kernel:
//  blocks 0..BB-1 : per-batch compaction (+ idx pad with 0, rsum zero,
//                   npad/kd32 computation)
//  blocks >= BB   : grid-stride fp32->fp16 convert of x + 3 weight matrices
// ---------------------------------------------------------------------------
static constexpr int CVT_F4   = 2883584;         // (8M + 3M) / 4
static constexpr int PREP_CVT = 1024;            // convert blocks

__global__ __launch_bounds__(256)
void prep_kernel(const int* __restrict__ mask, int* __restrict__ idx,
                 int* __restrict__ nkeepA, int* __restrict__ npadA,
                 int* __restrict__ kd32A, float* __restrict__ rsum,
                 const float* __restrict__ x,
                 const float* __restrict__ Wq, const float* __restrict__ Wk,
                 const float* __restrict__ Wv,
                 __half* __restrict__ xh, __half* __restrict__ Wqh,
                 __half* __restrict__ Wkvh)
{
    const int t = threadIdx.x;
    if (blockIdx.x < BB) {
        const int b = blockIdx.x;
        const int* m = mask + (size_t)b * SS;
        int* idxb = idx + (size_t)b * SS;
        __shared__ int cnt[257];
        int loc[8], c = 0;
#pragma unroll
        for (int i = 0; i < 8; i++) {
            loc[i] = (m[t * 8 + i] != 0);
            c += loc[i];
        }
        cnt[t + 1] = c;
        if (t == 0) cnt[0] = 0;
        __syncthreads();
        if (t == 0)
            for (int i = 1; i <= 256; i++) cnt[i] += cnt[i - 1];
        __syncthreads();
        int base = cnt[t];
#pragma unroll
        for (int i = 0; i < 8; i++)
            if (loc[i]) idxb[base++] = t * 8 + i;
        const int tot = cnt[256];
        // pad remaining index slots with 0 (its K/V values meet exactly-zero
        // probabilities, so any finite row index is correct)
        for (int i = tot + t; i < SS; i += 256) idxb[i] = 0;
        if (t == 0) {
            nkeepA[b] = tot;
            npadA[b]  = (tot + 127) & ~127;
            kd32A[b]  = (tot + 31) & ~31;
        }
        float4 z = make_float4(0.f, 0.f, 0.f, 0.f);
        ((float4*)rsum)[(b * 256 + t) * 2 + 0] = z;
        ((float4*)rsum)[(b * 256 + t) * 2 + 1] = z;
    } else {
        const int cblk = blockIdx.x - BB;
        for (int i = cblk * 256 + t; i < CVT_F4; i += PREP_CVT * 256) {
            const float* src;
            __half* dst;
            int k;
            if (i < 2097152) { src = x; dst = xh; k = i; }
            else {
                int j = i - 2097152;
                int w = j >> 18;
                k = j & 262143;
                src = (w == 0) ? Wq : (w == 1) ? Wk : Wv;
                dst = (w == 0) ? Wqh : (w == 1) ? Wkvh : (Wkvh + DD * DD);
            }
            float4 v = ((const float4*)src)[k];
            ((__half2*)dst)[2 * k + 0] =
                __halves2half2(__float2half_rn(v.x), __float2half_rn(v.y));
            ((__half2*)dst)[2 * k + 1] =
                __halves2half2(__float2half_rn(v.z), __float2half_rn(v.w));
        }
    }
}

// ---------------------------------------------------------------------------
extern "C" void kernel_launch(void* const* d_in, const int* in_sizes, int n_in,
                              void* d_out, int out_size)
{
    const float* x    = (const float*)d_in[0];
    const int*   mask = (const int*)  d_in[1];
    const float* Wq   = (const float*)d_in[2];
    const float* bq   = (const float*)d_in[3];
    const float* Wk   = (const float*)d_in[4];
    const float* bk   = (const float*)d_in[5];
    const float* Wv   = (const float*)d_in[6];
    const float* bv   = (const float*)d_in[7];
    float* out = (float*)d_out;

    __half *xh, *Wqh, *Wkvh, *Qh, *Kc, *Vtc, *Ph;
    float* rsum;
    int *idx, *nkeep, *npad, *kd32;
    cudaGetSymbolAddress((void**)&xh,   g_xh);
    cudaGetSymbolAddress((void**)&Wqh,  g_Wqh);
    cudaGetSymbolAddress((void**)&Wkvh, g_Wkvh);
    cudaGetSymbolAddress((void**)&Qh,   g_Qh);
    cudaGetSymbolAddress((void**)&Kc,   g_Kc);
    cudaGetSymbolAddress((void**)&Vtc,  g_Vtc);
    cudaGetSymbolAddress((void**)&Ph,   g_Ph);
    cudaGetSymbolAddress((void**)&rsum, g_rsum);
    cudaGetSymbolAddress((void**)&idx,  g_idx);
    cudaGetSymbolAddress((void**)&nkeep, g_nkeep);
    cudaGetSymbolAddress((void**)&npad, g_npad);
    cudaGetSymbolAddress((void**)&kd32, g_kd32);

    cudaFuncSetAttribute(hgemm<5>, cudaFuncAttributeMaxDynamicSharedMemorySize, SMEMB);
    cudaFuncSetAttribute(hgemm<6>, cudaFuncAttributeMaxDynamicSharedMemorySize, SMEMB);
    cudaFuncSetAttribute(hgemm<7>, cudaFuncAttributeMaxDynamicSharedMemorySize, SMEMB);

    const long long sBD = (long long)SS * DD;
    const long long sSS = (long long)SS * SS;

    // #0: compaction + rsum zero + converts (one launch)
    prep_kernel<<<BB + PREP_CVT, 256>>>(mask, idx, nkeep, npad, kd32, rsum,
                                        x, Wq, Wk, Wv, xh, Wqh, Wkvh);

    // #1: merged Q + K|V projections, packed grid (z = 6):
    //   z in [0,4): K|V proj batch z (x covers 2048 cols, rows < npad[z])
    //   z in [4,6): Q proj, seg = (z-4)*2 + (x>=8); each seg = 2048 rows
    {
        dim3 g(2 * DD / 128, SS / 128, BB + 2);
        hgemm<7><<<g, 256, SMEMB>>>(xh, Wkvh, bk, bv, nullptr, Kc, Vtc,
                                    nullptr, nullptr,
                                    DD, DD, DD, DD, 1.0f, sBD, 0, sBD,
                                    npad, nullptr, nullptr, idx,
                                    xh, Wqh, bq, Qh);
    }

    // #2: scores -> unnormalized exp fp16 + row sums
    {
        dim3 g(SS / 128, SS / 128, BB);
        hgemm<5><<<g, 256, SMEMB>>>(Qh, Kc, nullptr, nullptr, nullptr, Ph, nullptr,
                                    rsum, nkeep,
                                    DD, DD, SS, DD, 1.0f / 32.0f,
                                    sBD, sBD, sSS,
                                    nullptr, npad, nullptr, nullptr,
                                    nullptr, nullptr, nullptr, nullptr);
    }

    // #3: out = (E @ Vtc^T) / rsum[row], dynamic K = kd32[b]
    {
        dim3 g(DD / 128, SS / 128, BB);
        hgemm<6><<<g, 256, SMEMB>>>(Ph, Vtc, nullptr, nullptr, out, nullptr, nullptr,
                                    rsum, nullptr,
                                    SS, SS, DD, DD, 1.0f,
                                    sSS, sBD, sBD,
                                    nullptr, nullptr, kd32, nullptr,
                                    nullptr, nullptr, nullptr, nullptr);
    }
}